// round 12
// baseline (speedup 1.0000x reference)
#include <cuda_runtime.h>
#include <cstdint>

#define TSEQ 512
#define NB   64
#define NI   512
#define NH   1024
#define NHX  1536
#define NG   4096

// ---------------- scratch (no allocation allowed -> device globals) ----------------
__device__ float g_Gx[(size_t)TSEQ * NG * NB];     // [t][gate*NH+u][b]  x-part + bias
__device__ float g_hbuf[2][NB * NH];               // double-buffered hidden state [b][k]
__device__ unsigned g_bar_count;                   // zero-init at module load
__device__ unsigned g_bar_gen;

// ---------------- helpers ----------------
__device__ __forceinline__ unsigned long long lds64(const float* p) {
    return *reinterpret_cast<const unsigned long long*>(p);
}
__device__ __forceinline__ void fma2(unsigned long long& d, unsigned long long a,
                                     unsigned long long b) {
    asm("fma.rn.f32x2 %0, %1, %2, %0;" : "+l"(d) : "l"(a), "l"(b));
}
__device__ __forceinline__ float lo32(unsigned long long v) { return __uint_as_float((unsigned)v); }
__device__ __forceinline__ float hi32(unsigned long long v) { return __uint_as_float((unsigned)(v >> 32)); }
__device__ __forceinline__ float sigmoidf_(float v) { return 1.f / (1.f + __expf(-v)); }

// =====================================================================
// Phase 1: Gx[t][g*NH+u][b] = sum_k x[t][b][k] * W[g][u][NH+k] + bias
// Per-t GEMM 4096 x 64 x 512. 64x64 block tile, K-tile 32, 8x8 regs,
// 2-way K-split. DOUBLE-BUFFERED staging: STS(i+1) + LDG(i+2) overlap
// compute(i); ONE sync per k-tile.
// =====================================================================
__global__ __launch_bounds__(128, 2) void gx_gemm(
    const float* __restrict__ x,
    const float* __restrict__ Wf, const float* __restrict__ Wi,
    const float* __restrict__ Wc, const float* __restrict__ Wo,
    const float* __restrict__ bf, const float* __restrict__ bi,
    const float* __restrict__ bc, const float* __restrict__ bo)
{
    __shared__ float sW[2][64 * 36];   // [row][k]
    __shared__ float sX[2][64 * 36];   // [b][k]

    const int t    = blockIdx.y;
    const int jb   = blockIdx.x;          // 0..63 (16 blocks per gate)
    const int gate = jb >> 4;
    const int u0   = (jb & 15) << 6;

    const float* Wsrc = (gate == 0) ? Wf : (gate == 1) ? Wi : (gate == 2) ? Wc : Wo;
    const float* bsrc = (gate == 0) ? bf : (gate == 1) ? bi : (gate == 2) ? bc : bo;

    const int tid = threadIdx.x;          // 0..127
    const int kc  = tid & 1;              // K split
    const int bg  = (tid >> 1) & 7;       // b in {bg, bg+8, ..., bg+56}
    const int rg  = tid >> 4;             // rows rg*8 .. rg*8+7
    const int lr  = tid >> 3;             // loader row/batch
    const int lq  = tid & 7;              // loader k-quad

    unsigned long long acc[8][8];
#pragma unroll
    for (int i = 0; i < 8; i++)
#pragma unroll
        for (int j = 0; j < 8; j++) acc[i][j] = 0ULL;

    float4 wreg[4], xreg[4];

    // ---- load tile 0 regs, stage to buf0, load tile 1 regs ----
#pragma unroll
    for (int p = 0; p < 4; p++) {
        const int r = lr + p * 16;
        wreg[p] = *reinterpret_cast<const float4*>(Wsrc + (size_t)(u0 + r) * NHX + NH + lq * 4);
        xreg[p] = *reinterpret_cast<const float4*>(x + ((size_t)t * NB + r) * NI + lq * 4);
    }
#pragma unroll
    for (int p = 0; p < 4; p++) {
        const int r = lr + p * 16;
        *reinterpret_cast<float4*>(&sW[0][r * 36 + lq * 4]) = wreg[p];
        *reinterpret_cast<float2*>(&sX[0][r * 36 + lq * 4])     = make_float2(xreg[p].x, xreg[p].y);
        *reinterpret_cast<float2*>(&sX[0][r * 36 + lq * 4 + 2]) = make_float2(xreg[p].z, xreg[p].w);
    }
#pragma unroll
    for (int p = 0; p < 4; p++) {
        const int r = lr + p * 16;
        wreg[p] = *reinterpret_cast<const float4*>(Wsrc + (size_t)(u0 + r) * NHX + NH + 32 + lq * 4);
        xreg[p] = *reinterpret_cast<const float4*>(x + ((size_t)t * NB + r) * NI + 32 + lq * 4);
    }
    __syncthreads();

#pragma unroll 1
    for (int it = 0; it < 16; it++) {
        const float* cw = sW[it & 1];
        const float* cx = sX[it & 1];
        float* nw = sW[(it + 1) & 1];
        float* nx = sX[(it + 1) & 1];

        if (it < 15) {
#pragma unroll
            for (int p = 0; p < 4; p++) {
                const int r = lr + p * 16;
                *reinterpret_cast<float4*>(&nw[r * 36 + lq * 4]) = wreg[p];
                *reinterpret_cast<float2*>(&nx[r * 36 + lq * 4])     = make_float2(xreg[p].x, xreg[p].y);
                *reinterpret_cast<float2*>(&nx[r * 36 + lq * 4 + 2]) = make_float2(xreg[p].z, xreg[p].w);
            }
        }
        if (it < 14) {
            const int kt = (it + 2) * 32;
#pragma unroll
            for (int p = 0; p < 4; p++) {
                const int r = lr + p * 16;
                wreg[p] = *reinterpret_cast<const float4*>(
                    Wsrc + (size_t)(u0 + r) * NHX + NH + kt + lq * 4);
                xreg[p] = *reinterpret_cast<const float4*>(
                    x + ((size_t)t * NB + r) * NI + kt + lq * 4);
            }
        }

#pragma unroll 2
        for (int j = 0; j < 8; j++) {         // k-pair = 2j + kc
            unsigned long long wv[8], xv[8];
#pragma unroll
            for (int i = 0; i < 8; i++)
                wv[i] = lds64(&cw[(rg * 8 + i) * 36 + 4 * j + 2 * kc]);
#pragma unroll
            for (int jj = 0; jj < 8; jj++)
                xv[jj] = lds64(&cx[(bg + 8 * jj) * 36 + 4 * j + 2 * kc]);
#pragma unroll
            for (int i = 0; i < 8; i++)
#pragma unroll
                for (int jj = 0; jj < 8; jj++)
                    fma2(acc[i][jj], wv[i], xv[jj]);
        }
        __syncthreads();
    }

    // reduce halves + 1-round butterfly over kc (lane bit 0)
    float s[8][8];
#pragma unroll
    for (int i = 0; i < 8; i++)
#pragma unroll
        for (int jj = 0; jj < 8; jj++) {
            float v = lo32(acc[i][jj]) + hi32(acc[i][jj]);
            v += __shfl_xor_sync(0xffffffffu, v, 1);
            s[i][jj] = v;
        }

    // thread kc writes rows with i%2==kc; b strided (bg + 8*jj)
#pragma unroll
    for (int i = 0; i < 8; i++) {
        if ((i & 1) == kc) {
            const int row = rg * 8 + i;
            const float bias = bsrc[u0 + row];
            float* Cp = g_Gx + ((size_t)t * NG + (size_t)gate * NH + u0 + row) * NB;
#pragma unroll
            for (int jj = 0; jj < 8; jj++)
                Cp[bg + 8 * jj] = s[i][jj] + bias;
        }
    }
}

// =====================================================================
// Phase 2: persistent recurrent kernel. 128 CTAs x 256 threads.
// h stored [b][k] in global -> straight staged copy. DOUBLE-BUFFERED
// sH: STS(i+1) and LDG(i+2) overlap compute(i); ONE sync per k-tile
// (8/step instead of 16). Weights SMEM-resident all 512 steps.
// 8x8 reg tile, 8-way K-split + 3-round shfl butterfly.
// =====================================================================
#define SW_STRIDE 1032
#define SH_STRIDE 130
#define SG_STRIDE 68
// floats: sW 32*1032 = 33024 | sH0 8320 | sH1 8320 | sG 32*68 = 2176
#define OFF_H0 33024
#define OFF_H1 41344
#define OFF_G  49664
#define P2_SMEM ((OFF_G + 32 * SG_STRIDE) * 4)    // 207360 B

__device__ __forceinline__ void grid_barrier() {
    __threadfence();
    __syncthreads();
    if (threadIdx.x == 0) {
        volatile unsigned* vgen = &g_bar_gen;
        const unsigned gen = *vgen;
        const unsigned arrived = atomicAdd(&g_bar_count, 1u);
        if ((arrived & 127u) == 127u) {          // 128 divides 2^32: wrap-safe
            atomicAdd(&g_bar_gen, 1u);
        } else {
            while (*vgen == gen) { }
        }
    }
    __syncthreads();
    __threadfence();
}

__global__ __launch_bounds__(256, 1) void lstm_steps(
    const float* __restrict__ Wf, const float* __restrict__ Wi,
    const float* __restrict__ Wc, const float* __restrict__ Wo,
    float* __restrict__ out)
{
    extern __shared__ float smem[];
    float* sW  = smem;                     // 32 x 1032   weights, whole kernel
    float* sH0 = smem + OFF_H0;            // 64 x 130    h tile buffer 0
    float* sH1 = smem + OFF_H1;            // 64 x 130    h tile buffer 1
    float* sG  = smem + OFF_G;             // 32 x 68     staged gate pre-acts

    const int tid    = threadIdx.x;
    const int u_base = blockIdx.x * 8;

    // Load this CTA's 32 weight rows (h-part = cols [0, NH)) into SMEM once.
    for (int i = tid; i < 8192; i += 256) {       // 8192 float4s
        const int r = i >> 8, q = i & 255;
        const int g = r >> 3, ul = r & 7;
        const float* Wsrc = (g == 0) ? Wf : (g == 1) ? Wi : (g == 2) ? Wc : Wo;
        const float4 v = *reinterpret_cast<const float4*>(
            Wsrc + (size_t)(u_base + ul) * NHX + q * 4);
        *reinterpret_cast<float4*>(&sW[r * SW_STRIDE + q * 4]) = v;
    }
    // Zero h buffer 0 for owned columns (h_{-1} = 0), layout [b][k].
    for (int i = tid; i < 8 * NB; i += 256) {
        const int b = i >> 3, uc = i & 7;
        g_hbuf[0][(size_t)b * NH + u_base + uc] = 0.f;
    }

    // dot-phase mapping
    const int kc = tid & 7;                // K split slot
    const int bg = (tid >> 3) & 7;         // batches bg*8 .. bg*8+7
    const int rg = tid >> 6;               // gate; rows rg*8 .. rg*8+7
    // copy mapping: 16 float2/thread; b = cb + 4p, float2 slot ck2
    const int cb  = tid >> 6;              // 0..3
    const int ck2 = tid & 63;              // float2 slot within row (0..63)
    // combine mapping
    const int u_l = tid >> 5;
    const int bp  = tid & 31;
    const int b0  = bp * 2;
    float2 creg = make_float2(0.f, 0.f);

    grid_barrier();   // h0 zeros visible everywhere

    for (int t = 0; t < TSEQ; t++) {
        const float* hprev = g_hbuf[t & 1];
        float* hnext = g_hbuf[(t & 1) ^ 1];

        unsigned long long acc[8][8];
#pragma unroll
        for (int i = 0; i < 8; i++)
#pragma unroll
            for (int j = 0; j < 8; j++) acc[i][j] = 0ULL;

        float2 hreg[16];
        // tile 0 -> regs -> buf0; tile 1 -> regs
#pragma unroll
        for (int p = 0; p < 16; p++) {
            const int b = cb + p * 4;
            hreg[p] = __ldcg(reinterpret_cast<const float2*>(
                hprev + (size_t)b * NH + 2 * ck2));
        }
#pragma unroll
        for (int p = 0; p < 16; p++) {
            const int b = cb + p * 4;
            *reinterpret_cast<float2*>(&sH0[b * SH_STRIDE + 2 * ck2]) = hreg[p];
        }
#pragma unroll
        for (int p = 0; p < 16; p++) {
            const int b = cb + p * 4;
            hreg[p] = __ldcg(reinterpret_cast<const float2*>(
                hprev + (size_t)b * NH + 128 + 2 * ck2));
        }
        __syncthreads();

#pragma unroll 1
        for (int it = 0; it < 8; it++) {
            const int kt = it * 128;
            const float* buf = (it & 1) ? sH1 : sH0;
            float* nbuf = (it & 1) ? sH0 : sH1;

            // STS tile it+1 (regs from previous iteration) into the other buffer
            if (it < 7) {
#pragma unroll
                for (int p = 0; p < 16; p++) {
                    const int b = cb + p * 4;
                    *reinterpret_cast<float2*>(&nbuf[b * SH_STRIDE + 2 * ck2]) = hreg[p];
                }
            }
            // issue LDG tile it+2 (consumed next iteration; hidden under compute)
            if (it < 6) {
#pragma unroll
                for (int p = 0; p < 16; p++) {
                    const int b = cb + p * 4;
                    hreg[p] = __ldcg(reinterpret_cast<const float2*>(
                        hprev + (size_t)b * NH + kt + 256 + 2 * ck2));
                }
            }

            const float* wb = sW + rg * 8 * SW_STRIDE + kt + 2 * kc;
            const float* hb = buf + bg * 8 * SH_STRIDE + 2 * kc;
#pragma unroll 2
            for (int j = 0; j < 8; j++) {        // k-pair = 8j + kc
                unsigned long long wv[8], hv[8];
#pragma unroll
                for (int i = 0; i < 8; i++) wv[i] = lds64(wb + i * SW_STRIDE + 16 * j);
#pragma unroll
                for (int jj = 0; jj < 8; jj++) hv[jj] = lds64(hb + jj * SH_STRIDE + 16 * j);
#pragma unroll
                for (int i = 0; i < 8; i++)
#pragma unroll
                    for (int jj = 0; jj < 8; jj++)
                        fma2(acc[i][jj], wv[i], hv[jj]);
            }
            __syncthreads();   // ONE sync per tile
        }

        // reduce halves + 3-round butterfly over kc (lane bits 0..2)
        float s[8][8];
#pragma unroll
        for (int i = 0; i < 8; i++)
#pragma unroll
            for (int jj = 0; jj < 8; jj++) {
                float v = lo32(acc[i][jj]) + hi32(acc[i][jj]);
                v += __shfl_xor_sync(0xffffffffu, v, 1);
                v += __shfl_xor_sync(0xffffffffu, v, 2);
                v += __shfl_xor_sync(0xffffffffu, v, 4);
                s[i][jj] = v;
            }

        // thread kc writes its row (i == kc): static indexing, 2x STS.128
#pragma unroll
        for (int i = 0; i < 8; i++) {
            if (i == kc) {
                float* Gr = &sG[(rg * 8 + i) * SG_STRIDE + bg * 8];
                *reinterpret_cast<float4*>(Gr) =
                    make_float4(s[i][0], s[i][1], s[i][2], s[i][3]);
                *reinterpret_cast<float4*>(Gr + 4) =
                    make_float4(s[i][4], s[i][5], s[i][6], s[i][7]);
            }
        }
        __syncthreads();

        // combine: gates -> c, h; h stored [b][k] in global
        {
            const int u = u_base + u_l;
            const float* Gp = g_Gx + (size_t)t * NG * NB;
            const float2 hf = *reinterpret_cast<const float2*>(&sG[(0  + u_l) * SG_STRIDE + b0]);
            const float2 hi = *reinterpret_cast<const float2*>(&sG[(8  + u_l) * SG_STRIDE + b0]);
            const float2 hc = *reinterpret_cast<const float2*>(&sG[(16 + u_l) * SG_STRIDE + b0]);
            const float2 ho = *reinterpret_cast<const float2*>(&sG[(24 + u_l) * SG_STRIDE + b0]);
            const float2 xf = *reinterpret_cast<const float2*>(Gp + ((size_t)0 * NH + u) * NB + b0);
            const float2 xi = *reinterpret_cast<const float2*>(Gp + ((size_t)1 * NH + u) * NB + b0);
            const float2 xc = *reinterpret_cast<const float2*>(Gp + ((size_t)2 * NH + u) * NB + b0);
            const float2 xo = *reinterpret_cast<const float2*>(Gp + ((size_t)3 * NH + u) * NB + b0);

            const float fx = sigmoidf_(hf.x + xf.x), fy = sigmoidf_(hf.y + xf.y);
            const float ix = sigmoidf_(hi.x + xi.x), iy = sigmoidf_(hi.y + xi.y);
            const float cx = tanhf(hc.x + xc.x),     cy = tanhf(hc.y + xc.y);
            const float ox = sigmoidf_(ho.x + xo.x), oy = sigmoidf_(ho.y + xo.y);

            creg.x = fx * creg.x + ix * cx;
            creg.y = fy * creg.y + iy * cy;
            const float hx_ = ox * tanhf(creg.x);
            const float hy_ = oy * tanhf(creg.y);

            __stcg(hnext + (size_t)b0 * NH + u, hx_);
            __stcg(hnext + (size_t)(b0 + 1) * NH + u, hy_);
            out[((size_t)t * NB + b0) * NH + u]     = hx_;
            out[((size_t)t * NB + b0 + 1) * NH + u] = hy_;
        }

        grid_barrier();   // h_t visible before anyone reads it at t+1
    }
}

// =====================================================================
// launch
// =====================================================================
extern "C" void kernel_launch(void* const* d_in, const int* in_sizes, int n_in,
                              void* d_out, int out_size)
{
    const float* x  = (const float*)d_in[0];
    const float* Wf = (const float*)d_in[1];
    const float* bf = (const float*)d_in[2];
    const float* Wi = (const float*)d_in[3];
    const float* bi = (const float*)d_in[4];
    const float* Wc = (const float*)d_in[5];
    const float* bc = (const float*)d_in[6];
    const float* Wo = (const float*)d_in[7];
    const float* bo = (const float*)d_in[8];
    float* out = (float*)d_out;

    (void)in_sizes; (void)n_in; (void)out_size;

    cudaFuncSetAttribute(lstm_steps, cudaFuncAttributeMaxDynamicSharedMemorySize, P2_SMEM);

    gx_gemm<<<dim3(64, TSEQ), 128>>>(x, Wf, Wi, Wc, Wo, bf, bi, bc, bo);
    lstm_steps<<<128, 256, P2_SMEM>>>(Wf, Wi, Wc, Wo, out);
}